// round 9
// baseline (speedup 1.0000x reference)
#include <cuda_runtime.h>
#include <cuda_bf16.h>
#include <cstdint>

#define IN_F   512
#define OUT_F  512
#define NBAT   8192
#define NFEAT  12                      // 1 raw x + 11 spline bases
#define KB     (IN_F * NFEAT)          // 6144 (K of one hi/lo block)
#define ROWB   (KB * 2)                // 12288 B global row stride
#define NSEG   (KB / 64)               // 96 k-segments per block
#define NU     (3 * NSEG)              // 288 chunk iterations (3 products)
#define STG    4
#define M_TILE 128
#define N_TILE 256
#define A_BYTES 16384                  // 128 rows x 128 B
#define B_BYTES 32768                  // 256 rows x 128 B
#define STAGE_BYTES (A_BYTES + B_BYTES)           // 49152
#define SMEM_TOTAL  (STG * STAGE_BYTES)           // 196608

// ---------------- scratch (device globals: allocation-free) ----------------
__device__ __nv_bfloat16 g_Ah[(size_t)NBAT * KB];     // 100.7 MB
__device__ __nv_bfloat16 g_Al[(size_t)NBAT * KB];     // 100.7 MB
__device__ __nv_bfloat16 g_Bh[(size_t)OUT_F * KB];    // 6.3 MB
__device__ __nv_bfloat16 g_Bl[(size_t)OUT_F * KB];    // 6.3 MB

// ---------------- PTX helpers (base-sm_80+ only) ---------------------------
__device__ __forceinline__ uint32_t smem_u32(const void* p) {
    uint32_t a;
    asm("{ .reg .u64 t; cvta.to.shared.u64 t, %1; cvt.u32.u64 %0, t; }" : "=r"(a) : "l"(p));
    return a;
}
__device__ __forceinline__ void cp16(uint32_t dst, const void* src) {
    asm volatile("cp.async.cg.shared.global [%0], [%1], 16;" :: "r"(dst), "l"(src));
}
#define CP_COMMIT() asm volatile("cp.async.commit_group;" ::: "memory")
#define CP_WAIT_2() asm volatile("cp.async.wait_group 2;" ::: "memory")

__device__ __forceinline__ void ldsm4(uint32_t& r0, uint32_t& r1, uint32_t& r2,
                                      uint32_t& r3, uint32_t addr) {
    asm volatile("ldmatrix.sync.aligned.m8n8.x4.shared.b16 {%0,%1,%2,%3}, [%4];"
                 : "=r"(r0), "=r"(r1), "=r"(r2), "=r"(r3) : "r"(addr));
}
__device__ __forceinline__ void mma16816(float& d0, float& d1, float& d2, float& d3,
                                         uint32_t a0, uint32_t a1, uint32_t a2, uint32_t a3,
                                         uint32_t b0, uint32_t b1) {
    asm volatile(
        "mma.sync.aligned.m16n8k16.row.col.f32.bf16.bf16.f32 "
        "{%0,%1,%2,%3}, {%4,%5,%6,%7}, {%8,%9}, {%0,%1,%2,%3};"
        : "+f"(d0), "+f"(d1), "+f"(d2), "+f"(d3)
        : "r"(a0), "r"(a1), "r"(a2), "r"(a3), "r"(b0), "r"(b1));
}
// 128-byte smem rows, XOR-(r&7) swizzle; k16 step s = XOR (s<<5) on the address.
__device__ __forceinline__ uint32_t swz(int r, int c) {
    return (uint32_t)(r * 128 + ((c ^ (r & 7)) << 4));
}

// ---------------- basis (identical math to all passing kernels) ------------
__device__ __forceinline__ void aug_features(float xr, float* bb) {
    float xc = fminf(fmaxf(xr, -2.0f), 2.0f);
    float g[15];
#pragma unroll
    for (int m = 0; m < 15; ++m) g[m] = fmaf((float)m, 2.0f / 14.0f, -1.0f);
    float b[14];
#pragma unroll
    for (int m = 0; m < 14; ++m) b[m] = (xc >= g[m] && xc < g[m + 1]) ? 1.0f : 0.0f;
#pragma unroll
    for (int k = 1; k <= 3; ++k) {
        float inv = 7.0f / (float)k;
#pragma unroll
        for (int m = 0; m < 14 - k; ++m)
            b[m] = (xc - g[m]) * inv * b[m] + (g[m + k + 1] - xc) * inv * b[m + 1];
    }
    bb[0] = xr;
#pragma unroll
    for (int j = 0; j < 11; ++j) bb[1 + j] = b[j];
}
__device__ __forceinline__ void pack3(const unsigned short* s, unsigned long long* w) {
#pragma unroll
    for (int j = 0; j < 3; ++j)
        w[j] = (unsigned long long)s[4 * j] |
               ((unsigned long long)s[4 * j + 1] << 16) |
               ((unsigned long long)s[4 * j + 2] << 32) |
               ((unsigned long long)s[4 * j + 3] << 48);
}

// ---------------- prep_B: weights -> hi/lo blocks --------------------------
__global__ __launch_bounds__(256) void prep_B(const float* __restrict__ bw,
                                              const float* __restrict__ sw) {
    int idx = blockIdx.x * 256 + threadIdx.x;        // (o, i)
    int o = idx >> 9, i = idx & 511;
    float v[NFEAT];
    v[0] = bw[(size_t)o * IN_F + i];
#pragma unroll
    for (int j = 0; j < 11; ++j) v[1 + j] = sw[((size_t)o * IN_F + i) * 11 + j];
    unsigned short sh[NFEAT], sl[NFEAT];
#pragma unroll
    for (int c = 0; c < NFEAT; ++c) {
        __nv_bfloat16 h = __float2bfloat16(v[c]);
        __nv_bfloat16 l = __float2bfloat16(v[c] - __bfloat162float(h));
        sh[c] = __bfloat16_as_ushort(h);  sl[c] = __bfloat16_as_ushort(l);
    }
    unsigned long long wh[3], wl[3];
    pack3(sh, wh);  pack3(sl, wl);
    size_t off = (size_t)o * KB + (size_t)i * NFEAT;
    unsigned long long* dh = (unsigned long long*)(g_Bh + off);
    unsigned long long* dl = (unsigned long long*)(g_Bl + off);
#pragma unroll
    for (int j = 0; j < 3; ++j) { dh[j] = wh[j];  dl[j] = wl[j]; }
}

// ---------------- fused GEMM -----------------------------------------------
// CTA 128x256, 8 warps 2(M) x 4(N), warp tile 64x64.
// Prologue builds this CTA's A_hi/A_lo slice.  Mainloop: 288 uniform chunks,
// chunk u -> product (u%3): (Ah,Bh),(Ah,Bl),(Al,Bh) at k-offset (u/3)*64.
// 4-stage cp.async pipeline, ONE barrier per chunk, k-step double buffering.
__global__ __launch_bounds__(256, 1) void kan_gemm(const float* __restrict__ x,
                                                   float* __restrict__ out) {
    extern __shared__ __align__(1024) unsigned char smem[];
    const uint32_t sbase = smem_u32(smem);
    const int tid  = threadIdx.x;
    const int lane = tid & 31;
    const int wid  = tid >> 5;
    const int warpM = wid & 1;
    const int warpN = wid >> 1;
    const int mBase = blockIdx.y * M_TILE;
    const int nBase = blockIdx.x * N_TILE;

    // ---- prologue: build this CTA's split-A slice in global scratch -------
    {
        const float* xrow = x + (size_t)mBase * IN_F;
#pragma unroll 1
        for (int j = 0; j < (M_TILE * IN_F) / 256; ++j) {   // 256 iters
            int idx = j * 256 + tid;
            int m = idx >> 9, i = idx & 511;
            float bb[NFEAT];
            aug_features(xrow[idx], bb);
            unsigned short sh[NFEAT], sl[NFEAT];
#pragma unroll
            for (int c = 0; c < NFEAT; ++c) {
                __nv_bfloat16 h = __float2bfloat16(bb[c]);
                __nv_bfloat16 l = __float2bfloat16(bb[c] - __bfloat162float(h));
                sh[c] = __bfloat16_as_ushort(h);  sl[c] = __bfloat16_as_ushort(l);
            }
            unsigned long long wh[3], wl[3];
            pack3(sh, wh);  pack3(sl, wl);
            size_t off = (size_t)(mBase + m) * KB + (size_t)i * NFEAT;
            unsigned long long* dh = (unsigned long long*)(g_Ah + off);
            unsigned long long* dl = (unsigned long long*)(g_Al + off);
#pragma unroll
            for (int q = 0; q < 3; ++q) { dh[q] = wh[q];  dl[q] = wl[q]; }
        }
        __threadfence();          // L2-visible before cp.async.cg reads them back
        __syncthreads();
    }

    const char* Ah = (const char*)(g_Ah + (size_t)mBase * KB);
    const char* Al = (const char*)(g_Al + (size_t)mBase * KB);
    const char* Bh = (const char*)(g_Bh + (size_t)nBase * KB);
    const char* Bl = (const char*)(g_Bl + (size_t)nBase * KB);

    // ---- cp.async coords: granule (r, c); thread t handles c = t&7 --------
    const int gr = tid >> 3, gc = tid & 7;
    uint32_t aDst[4], bDst[8];
#pragma unroll
    for (int j = 0; j < 4; ++j) aDst[j] = swz(gr + 32 * j, gc);
#pragma unroll
    for (int j = 0; j < 8; ++j) bDst[j] = (uint32_t)A_BYTES + swz(gr + 32 * j, gc);
    const uint32_t gOff = (uint32_t)gc * 16;

    auto load_stage = [&](int u) {
        const uint32_t st = sbase + (uint32_t)(u & (STG - 1)) * STAGE_BYTES;
        const int sel = u % 3;
        const size_t ch = (size_t)(u / 3) * 128;
        const char* aB = (sel < 2 ? Ah : Al) + ch;
        const char* bB = (sel == 1 ? Bl : Bh) + ch;
#pragma unroll
        for (int j = 0; j < 4; ++j)
            cp16(st + aDst[j], aB + (size_t)(gr + 32 * j) * ROWB + gOff);
#pragma unroll
        for (int j = 0; j < 8; ++j)
            cp16(st + bDst[j], bB + (size_t)(gr + 32 * j) * ROWB + gOff);
    };

    // ---- ldmatrix lane addressing (k-step advance = XOR (s<<5)) -----------
    const int lr = lane & 15;
    const int lc = lane >> 4;
    uint32_t aOff[4], bOff[4];
#pragma unroll
    for (int t = 0; t < 4; ++t) {
        aOff[t] = swz(warpM * 64 + t * 16 + lr, lc);
        bOff[t] = (uint32_t)A_BYTES + swz(warpN * 64 + t * 16 + lr, lc);
    }

    float acc[4][8][4];
#pragma unroll
    for (int mt = 0; mt < 4; ++mt)
#pragma unroll
        for (int nt = 0; nt < 8; ++nt)
#pragma unroll
            for (int q = 0; q < 4; ++q) acc[mt][nt][q] = 0.0f;

    for (int i = 0; i < STG - 1; ++i) { load_stage(i); CP_COMMIT(); }

#pragma unroll 1
    for (int i = 0; i < NU; ++i) {
        CP_WAIT_2();                 // chunk i resident (2 newer groups pending)
        __syncthreads();             // all warps done with the slot being refilled
        const int nc = i + STG - 1;
        if (nc < NU) load_stage(nc);
        CP_COMMIT();                 // one group per iter (may be empty)

        const uint32_t st = sbase + (uint32_t)(i & (STG - 1)) * STAGE_BYTES;

        uint32_t a[2][4][4], b[2][4][4];
#pragma unroll
        for (int t = 0; t < 4; ++t) {                 // k-step 0 frags
            ldsm4(a[0][t][0], a[0][t][1], a[0][t][2], a[0][t][3], st + aOff[t]);
            ldsm4(b[0][t][0], b[0][t][1], b[0][t][2], b[0][t][3], st + bOff[t]);
        }
#pragma unroll
        for (int s = 0; s < 4; ++s) {
            const int cur = s & 1, nxt = cur ^ 1;
            if (s < 3) {
                const uint32_t kx = (uint32_t)(s + 1) << 5;
#pragma unroll
                for (int t = 0; t < 4; ++t) {
                    ldsm4(a[nxt][t][0], a[nxt][t][1], a[nxt][t][2], a[nxt][t][3],
                          st + (aOff[t] ^ kx));
                    ldsm4(b[nxt][t][0], b[nxt][t][1], b[nxt][t][2], b[nxt][t][3],
                          st + (bOff[t] ^ kx));
                }
            }
#pragma unroll
            for (int mt = 0; mt < 4; ++mt)
#pragma unroll
                for (int t = 0; t < 4; ++t) {
                    mma16816(acc[mt][2*t][0], acc[mt][2*t][1], acc[mt][2*t][2], acc[mt][2*t][3],
                             a[cur][mt][0], a[cur][mt][1], a[cur][mt][2], a[cur][mt][3],
                             b[cur][t][0], b[cur][t][2]);
                    mma16816(acc[mt][2*t+1][0], acc[mt][2*t+1][1], acc[mt][2*t+1][2], acc[mt][2*t+1][3],
                             a[cur][mt][0], a[cur][mt][1], a[cur][mt][2], a[cur][mt][3],
                             b[cur][t][1], b[cur][t][3]);
                }
        }
    }

    // ---- epilogue: direct STG of register accumulators --------------------
    const int mRow = mBase + warpM * 64 + (lane >> 2);
    const int nCol = nBase + warpN * 64 + (lane & 3) * 2;
#pragma unroll
    for (int mt = 0; mt < 4; ++mt) {
        float* r0 = out + (size_t)(mRow + mt * 16)     * OUT_F + nCol;
        float* r1 = out + (size_t)(mRow + mt * 16 + 8) * OUT_F + nCol;
#pragma unroll
        for (int nt = 0; nt < 8; ++nt) {
            *(float2*)(r0 + nt * 8) = make_float2(acc[mt][nt][0], acc[mt][nt][1]);
            *(float2*)(r1 + nt * 8) = make_float2(acc[mt][nt][2], acc[mt][nt][3]);
        }
    }
}

// ---------------- launch ---------------------------------------------------
extern "C" void kernel_launch(void* const* d_in, const int* in_sizes, int n_in,
                              void* d_out, int out_size) {
    const float* x  = (const float*)d_in[0];
    const float* bw = (const float*)d_in[1];
    const float* sw = (const float*)d_in[2];
    float* out = (float*)d_out;

    cudaFuncSetAttribute(kan_gemm, cudaFuncAttributeMaxDynamicSharedMemorySize,
                         SMEM_TOTAL);

    prep_B<<<(OUT_F * IN_F) / 256, 256>>>(bw, sw);
    kan_gemm<<<dim3(OUT_F / N_TILE, NBAT / M_TILE), 256, SMEM_TOTAL>>>(x, out);
}

// round 10
// speedup vs baseline: 1.3391x; 1.3391x over previous
#include <cuda_runtime.h>
#include <cuda_bf16.h>
#include <cstdint>

#define IN_F   512
#define OUT_F  512
#define NBAT   8192
#define NFEAT  12                      // 1 raw x + 11 spline bases
#define SLOTS  3                       // bf16 split: A=[hi,lo,hi], B=[hi,hi,lo]
#define KAUG   (IN_F * NFEAT * SLOTS)  // 18432
#define NCH    (KAUG / 64)             // 288 chunks (128 B each)
#define STG    4
#define M_TILE 128
#define N_TILE 256
#define ROWB   (KAUG * 2)              // global row stride in bytes
#define A_BYTES (M_TILE * 128)                    // 16 KB
#define B_BYTES (N_TILE * 128)                    // 32 KB
#define STAGE_BYTES (A_BYTES + B_BYTES)           // 49152
#define SMEM_TOTAL  (STG * STAGE_BYTES)           // 196608

// ---------------- scratch (device globals: allocation-free) ----------------
__device__ __nv_bfloat16 g_A[(size_t)NBAT * KAUG];    // 302 MB
__device__ __nv_bfloat16 g_B[(size_t)OUT_F * KAUG];   // 19 MB

// ---------------- PTX helpers (base-sm_80+ only) ---------------------------
__device__ __forceinline__ uint32_t smem_u32(const void* p) {
    uint32_t a;
    asm("{ .reg .u64 t; cvta.to.shared.u64 t, %1; cvt.u32.u64 %0, t; }" : "=r"(a) : "l"(p));
    return a;
}
__device__ __forceinline__ void cp16(uint32_t dst, const void* src) {
    asm volatile("cp.async.cg.shared.global [%0], [%1], 16;" :: "r"(dst), "l"(src));
}
#define CP_COMMIT() asm volatile("cp.async.commit_group;" ::: "memory")
#define CP_WAIT_2() asm volatile("cp.async.wait_group 2;" ::: "memory")

__device__ __forceinline__ void ldsm4(uint32_t& r0, uint32_t& r1, uint32_t& r2,
                                      uint32_t& r3, uint32_t addr) {
    asm volatile("ldmatrix.sync.aligned.m8n8.x4.shared.b16 {%0,%1,%2,%3}, [%4];"
                 : "=r"(r0), "=r"(r1), "=r"(r2), "=r"(r3) : "r"(addr));
}
__device__ __forceinline__ void mma16816(float& d0, float& d1, float& d2, float& d3,
                                         uint32_t a0, uint32_t a1, uint32_t a2, uint32_t a3,
                                         uint32_t b0, uint32_t b1) {
    asm volatile(
        "mma.sync.aligned.m16n8k16.row.col.f32.bf16.bf16.f32 "
        "{%0,%1,%2,%3}, {%4,%5,%6,%7}, {%8,%9}, {%0,%1,%2,%3};"
        : "+f"(d0), "+f"(d1), "+f"(d2), "+f"(d3)
        : "r"(a0), "r"(a1), "r"(a2), "r"(a3), "r"(b0), "r"(b1));
}
// 128-byte smem rows, XOR-(r&7) swizzle; k16 step s = XOR (s<<5) on the address.
__device__ __forceinline__ uint32_t swz(int r, int c) {
    return (uint32_t)(r * 128 + ((c ^ (r & 7)) << 4));
}

// ---------------- basis (identical math to all passing kernels) ------------
__device__ __forceinline__ void aug_features(float xr, float* bb) {
    float xc = fminf(fmaxf(xr, -2.0f), 2.0f);
    float g[15];
#pragma unroll
    for (int m = 0; m < 15; ++m) g[m] = fmaf((float)m, 2.0f / 14.0f, -1.0f);
    float b[14];
#pragma unroll
    for (int m = 0; m < 14; ++m) b[m] = (xc >= g[m] && xc < g[m + 1]) ? 1.0f : 0.0f;
#pragma unroll
    for (int k = 1; k <= 3; ++k) {
        float inv = 7.0f / (float)k;
#pragma unroll
        for (int m = 0; m < 14 - k; ++m)
            b[m] = (xc - g[m]) * inv * b[m] + (g[m + k + 1] - xc) * inv * b[m + 1];
    }
    bb[0] = xr;
#pragma unroll
    for (int j = 0; j < 11; ++j) bb[1 + j] = b[j];
}

// ---------------- P1: activations -> split-bf16 A (2 features/thread) -----
__global__ __launch_bounds__(256) void prep_A(const float* __restrict__ x) {
    int p  = blockIdx.x * 256 + threadIdx.x;
    int m  = p >> 8;
    int ip = (p & 255) * 2;

    float2 xv = *(const float2*)&x[(size_t)m * IN_F + ip];
    uint32_t w[36];
#pragma unroll
    for (int f = 0; f < 2; ++f) {
        float bb[NFEAT];
        aug_features(f ? xv.y : xv.x, bb);
        unsigned short s[NFEAT * SLOTS];
#pragma unroll
        for (int c = 0; c < NFEAT; ++c) {
            float v = bb[c];
            __nv_bfloat16 h = __float2bfloat16(v);
            __nv_bfloat16 l = __float2bfloat16(v - __bfloat162float(h));
            unsigned short hb = __bfloat16_as_ushort(h), lb = __bfloat16_as_ushort(l);
            s[3 * c + 0] = hb;  s[3 * c + 1] = lb;  s[3 * c + 2] = hb;  // A: [hi,lo,hi]
        }
#pragma unroll
        for (int k = 0; k < 18; ++k)
            w[f * 18 + k] = (uint32_t)s[2 * k] | ((uint32_t)s[2 * k + 1] << 16);
    }
    uint4* dst = (uint4*)(g_A + (size_t)m * KAUG + (size_t)ip * (NFEAT * SLOTS));
#pragma unroll
    for (int j = 0; j < 9; ++j)
        dst[j] = make_uint4(w[4 * j], w[4 * j + 1], w[4 * j + 2], w[4 * j + 3]);
}

// ---------------- P2: weights -> split-bf16 B ------------------------------
__global__ __launch_bounds__(256) void prep_B(const float* __restrict__ bw,
                                              const float* __restrict__ sw) {
    int idx = blockIdx.x * 256 + threadIdx.x;        // (o, i)
    int o = idx >> 9, i = idx & 511;
    float v[NFEAT];
    v[0] = bw[(size_t)o * IN_F + i];
#pragma unroll
    for (int j = 0; j < 11; ++j) v[1 + j] = sw[((size_t)o * IN_F + i) * 11 + j];
    unsigned short s[NFEAT * SLOTS];
#pragma unroll
    for (int c = 0; c < NFEAT; ++c) {
        __nv_bfloat16 h = __float2bfloat16(v[c]);
        __nv_bfloat16 l = __float2bfloat16(v[c] - __bfloat162float(h));
        unsigned short hb = __bfloat16_as_ushort(h), lb = __bfloat16_as_ushort(l);
        s[3 * c + 0] = hb;  s[3 * c + 1] = hb;  s[3 * c + 2] = lb;     // B: [hi,hi,lo]
    }
    unsigned long long* dst =
        (unsigned long long*)(g_B + (size_t)o * KAUG + (size_t)i * (NFEAT * SLOTS));
#pragma unroll
    for (int j = 0; j < 9; ++j)
        dst[j] = (unsigned long long)s[4 * j] |
                 ((unsigned long long)s[4 * j + 1] << 16) |
                 ((unsigned long long)s[4 * j + 2] << 32) |
                 ((unsigned long long)s[4 * j + 3] << 48);
}

// ---------------- G: mma.sync bf16 GEMM, 512 threads, 16 warps -------------
// CTA 128x256, warps 4(M) x 4(N), warp tile 32x64, k64 chunks, 4 stages,
// one barrier per chunk.  4 warps/SMSP hide LDSM/MMA latency (no k-step
// register double-buffering needed).
__global__ __launch_bounds__(512, 1) void kan_gemm(float* __restrict__ out) {
    extern __shared__ __align__(1024) unsigned char smem[];
    const uint32_t sbase = smem_u32(smem);
    const int tid  = threadIdx.x;
    const int lane = tid & 31;
    const int wid  = tid >> 5;
    const int warpM = wid & 3;          // 0..3 -> 32-row slice
    const int warpN = wid >> 2;         // 0..3 -> 64-col slice
    const int mBase = blockIdx.y * M_TILE;
    const int nBase = blockIdx.x * N_TILE;

    const char* Ag = (const char*)(g_A + (size_t)mBase * KAUG);
    const char* Bg = (const char*)(g_B + (size_t)nBase * KAUG);

    // ---- cp.async coords: 512 threads, granule (r, c) = (tid>>3, tid&7) ---
    const int gr = tid >> 3, gc = tid & 7;            // gr 0..63
    const char* aSrc[2];  uint32_t aDst[2];
#pragma unroll
    for (int j = 0; j < 2; ++j) {                     // A: 1024 granules
        int r = gr + 64 * j;
        aSrc[j] = Ag + (size_t)r * ROWB + gc * 16;
        aDst[j] = swz(r, gc);
    }
    const char* bSrc[4];  uint32_t bDst[4];
#pragma unroll
    for (int j = 0; j < 4; ++j) {                     // B: 2048 granules
        int r = gr + 64 * j;
        bSrc[j] = Bg + (size_t)r * ROWB + gc * 16;
        bDst[j] = (uint32_t)A_BYTES + swz(r, gc);
    }

    auto load_stage = [&](int ch) {
        const uint32_t st = sbase + (uint32_t)(ch & (STG - 1)) * STAGE_BYTES;
        const size_t off = (size_t)ch * 128;
#pragma unroll
        for (int j = 0; j < 2; ++j) cp16(st + aDst[j], aSrc[j] + off);
#pragma unroll
        for (int j = 0; j < 4; ++j) cp16(st + bDst[j], bSrc[j] + off);
    };

    // ---- ldmatrix lane addressing (k-step advance = XOR (s<<5)) -----------
    const int lr = lane & 15;
    const int lc = lane >> 4;
    uint32_t aOff[2], bOff[4];
#pragma unroll
    for (int t = 0; t < 2; ++t)
        aOff[t] = swz(warpM * 32 + t * 16 + lr, lc);
#pragma unroll
    for (int t = 0; t < 4; ++t)
        bOff[t] = (uint32_t)A_BYTES + swz(warpN * 64 + t * 16 + lr, lc);

    float acc[2][8][4];
#pragma unroll
    for (int mt = 0; mt < 2; ++mt)
#pragma unroll
        for (int nt = 0; nt < 8; ++nt)
#pragma unroll
            for (int q = 0; q < 4; ++q) acc[mt][nt][q] = 0.0f;

    for (int i = 0; i < STG - 1; ++i) { load_stage(i); CP_COMMIT(); }

#pragma unroll 1
    for (int i = 0; i < NCH; ++i) {
        CP_WAIT_2();                 // chunk i resident (2 newer groups pending)
        __syncthreads();             // all warps done with the slot being refilled
        const int nc = i + STG - 1;
        if (nc < NCH) load_stage(nc);
        CP_COMMIT();                 // one group per iter (may be empty)

        const uint32_t st = sbase + (uint32_t)(i & (STG - 1)) * STAGE_BYTES;
#pragma unroll
        for (int s = 0; s < 4; ++s) {
            const uint32_t kx = (uint32_t)s << 5;
            uint32_t a[2][4], b[4][4];
#pragma unroll
            for (int t = 0; t < 2; ++t)
                ldsm4(a[t][0], a[t][1], a[t][2], a[t][3], st + (aOff[t] ^ kx));
#pragma unroll
            for (int t = 0; t < 4; ++t)
                ldsm4(b[t][0], b[t][1], b[t][2], b[t][3], st + (bOff[t] ^ kx));
#pragma unroll
            for (int mt = 0; mt < 2; ++mt)
#pragma unroll
                for (int t = 0; t < 4; ++t) {
                    mma16816(acc[mt][2*t][0], acc[mt][2*t][1], acc[mt][2*t][2], acc[mt][2*t][3],
                             a[mt][0], a[mt][1], a[mt][2], a[mt][3], b[t][0], b[t][2]);
                    mma16816(acc[mt][2*t+1][0], acc[mt][2*t+1][1], acc[mt][2*t+1][2], acc[mt][2*t+1][3],
                             a[mt][0], a[mt][1], a[mt][2], a[mt][3], b[t][1], b[t][3]);
                }
        }
    }

    // ---- epilogue: direct STG of register accumulators --------------------
    const int mRow = mBase + warpM * 32 + (lane >> 2);
    const int nCol = nBase + warpN * 64 + (lane & 3) * 2;
#pragma unroll
    for (int mt = 0; mt < 2; ++mt) {
        float* r0 = out + (size_t)(mRow + mt * 16)     * OUT_F + nCol;
        float* r1 = out + (size_t)(mRow + mt * 16 + 8) * OUT_F + nCol;
#pragma unroll
        for (int nt = 0; nt < 8; ++nt) {
            *(float2*)(r0 + nt * 8) = make_float2(acc[mt][nt][0], acc[mt][nt][1]);
            *(float2*)(r1 + nt * 8) = make_float2(acc[mt][nt][2], acc[mt][nt][3]);
        }
    }
}

// ---------------- launch ---------------------------------------------------
extern "C" void kernel_launch(void* const* d_in, const int* in_sizes, int n_in,
                              void* d_out, int out_size) {
    const float* x  = (const float*)d_in[0];
    const float* bw = (const float*)d_in[1];
    const float* sw = (const float*)d_in[2];
    float* out = (float*)d_out;

    cudaFuncSetAttribute(kan_gemm, cudaFuncAttributeMaxDynamicSharedMemorySize,
                         SMEM_TOTAL);

    prep_A<<<(NBAT * IN_F / 2) / 256, 256>>>(x);
    prep_B<<<(OUT_F * IN_F) / 256, 256>>>(bw, sw);
    kan_gemm<<<dim3(OUT_F / N_TILE, NBAT / M_TILE), 512, SMEM_TOTAL>>>(out);
}

// round 11
// speedup vs baseline: 1.4159x; 1.0573x over previous
#include <cuda_runtime.h>
#include <cuda_bf16.h>
#include <cstdint>

#define IN_F   512
#define OUT_F  512
#define NBAT   8192
#define NFEAT  12                      // 1 raw x + 11 spline bases
#define KB     (IN_F * NFEAT)          // 6144 (K of one hi/lo block)
#define ROWB   (KB * 2)                // 12288 B global row stride
#define NSEG   (KB / 64)               // 96 k-segments per block
#define NCH    (3 * NSEG)              // 288 chunk iterations (3 products)
#define STG    4
#define M_TILE 128
#define N_TILE 256
#define A_BYTES (M_TILE * 128)                    // 16 KB
#define B_BYTES (N_TILE * 128)                    // 32 KB
#define STAGE_BYTES (A_BYTES + B_BYTES)           // 49152
#define SMEM_TOTAL  (STG * STAGE_BYTES)           // 196608

// ---------------- scratch (device globals: allocation-free) ----------------
__device__ __nv_bfloat16 g_Ah[(size_t)NBAT * KB];     // 100.7 MB
__device__ __nv_bfloat16 g_Al[(size_t)NBAT * KB];     // 100.7 MB
__device__ __nv_bfloat16 g_Bh[(size_t)OUT_F * KB];    // 6.3 MB
__device__ __nv_bfloat16 g_Bl[(size_t)OUT_F * KB];    // 6.3 MB

// ---------------- PTX helpers (base-sm_80+ only) ---------------------------
__device__ __forceinline__ uint32_t smem_u32(const void* p) {
    uint32_t a;
    asm("{ .reg .u64 t; cvta.to.shared.u64 t, %1; cvt.u32.u64 %0, t; }" : "=r"(a) : "l"(p));
    return a;
}
__device__ __forceinline__ void cp16(uint32_t dst, const void* src) {
    asm volatile("cp.async.cg.shared.global [%0], [%1], 16;" :: "r"(dst), "l"(src));
}
#define CP_COMMIT() asm volatile("cp.async.commit_group;" ::: "memory")
#define CP_WAIT_2() asm volatile("cp.async.wait_group 2;" ::: "memory")

__device__ __forceinline__ void ldsm4(uint32_t& r0, uint32_t& r1, uint32_t& r2,
                                      uint32_t& r3, uint32_t addr) {
    asm volatile("ldmatrix.sync.aligned.m8n8.x4.shared.b16 {%0,%1,%2,%3}, [%4];"
                 : "=r"(r0), "=r"(r1), "=r"(r2), "=r"(r3) : "r"(addr));
}
__device__ __forceinline__ void mma16816(float& d0, float& d1, float& d2, float& d3,
                                         uint32_t a0, uint32_t a1, uint32_t a2, uint32_t a3,
                                         uint32_t b0, uint32_t b1) {
    asm volatile(
        "mma.sync.aligned.m16n8k16.row.col.f32.bf16.bf16.f32 "
        "{%0,%1,%2,%3}, {%4,%5,%6,%7}, {%8,%9}, {%0,%1,%2,%3};"
        : "+f"(d0), "+f"(d1), "+f"(d2), "+f"(d3)
        : "r"(a0), "r"(a1), "r"(a2), "r"(a3), "r"(b0), "r"(b1));
}
// 128-byte smem rows, XOR-(r&7) swizzle; k16 step s = XOR (s<<5) on the address.
__device__ __forceinline__ uint32_t swz(int r, int c) {
    return (uint32_t)(r * 128 + ((c ^ (r & 7)) << 4));
}

// ---------------- basis (identical math to all passing kernels) ------------
__device__ __forceinline__ void aug_features(float xr, float* bb) {
    float xc = fminf(fmaxf(xr, -2.0f), 2.0f);
    float g[15];
#pragma unroll
    for (int m = 0; m < 15; ++m) g[m] = fmaf((float)m, 2.0f / 14.0f, -1.0f);
    float b[14];
#pragma unroll
    for (int m = 0; m < 14; ++m) b[m] = (xc >= g[m] && xc < g[m + 1]) ? 1.0f : 0.0f;
#pragma unroll
    for (int k = 1; k <= 3; ++k) {
        float inv = 7.0f / (float)k;
#pragma unroll
        for (int m = 0; m < 14 - k; ++m)
            b[m] = (xc - g[m]) * inv * b[m] + (g[m + k + 1] - xc) * inv * b[m + 1];
    }
    bb[0] = xr;
#pragma unroll
    for (int j = 0; j < 11; ++j) bb[1 + j] = b[j];
}

// ---------------- P1: activations -> A_hi / A_lo (2 features/thread) -------
__global__ __launch_bounds__(256) void prep_A(const float* __restrict__ x) {
    int p  = blockIdx.x * 256 + threadIdx.x;
    int m  = p >> 8;
    int ip = (p & 255) * 2;                          // even feature index

    float2 xv = *(const float2*)&x[(size_t)m * IN_F + ip];
    uint32_t wh[12], wl[12];                         // 24 bf16 each, packed u32
#pragma unroll
    for (int f = 0; f < 2; ++f) {
        float bb[NFEAT];
        aug_features(f ? xv.y : xv.x, bb);
        unsigned short sh[NFEAT], sl[NFEAT];
#pragma unroll
        for (int c = 0; c < NFEAT; ++c) {
            __nv_bfloat16 h = __float2bfloat16(bb[c]);
            __nv_bfloat16 l = __float2bfloat16(bb[c] - __bfloat162float(h));
            sh[c] = __bfloat16_as_ushort(h);  sl[c] = __bfloat16_as_ushort(l);
        }
#pragma unroll
        for (int k = 0; k < 6; ++k) {
            wh[f * 6 + k] = (uint32_t)sh[2 * k] | ((uint32_t)sh[2 * k + 1] << 16);
            wl[f * 6 + k] = (uint32_t)sl[2 * k] | ((uint32_t)sl[2 * k + 1] << 16);
        }
    }
    // 48 contiguous bytes per block, 16B-aligned (offset = 48 * pair)
    size_t off = (size_t)m * KB + (size_t)ip * NFEAT;
    uint4* dh = (uint4*)(g_Ah + off);
    uint4* dl = (uint4*)(g_Al + off);
#pragma unroll
    for (int j = 0; j < 3; ++j) {
        dh[j] = make_uint4(wh[4 * j], wh[4 * j + 1], wh[4 * j + 2], wh[4 * j + 3]);
        dl[j] = make_uint4(wl[4 * j], wl[4 * j + 1], wl[4 * j + 2], wl[4 * j + 3]);
    }
}

// ---------------- P2: weights -> B_hi / B_lo -------------------------------
__global__ __launch_bounds__(256) void prep_B(const float* __restrict__ bw,
                                              const float* __restrict__ sw) {
    int idx = blockIdx.x * 256 + threadIdx.x;        // (o, i)
    int o = idx >> 9, i = idx & 511;
    float v[NFEAT];
    v[0] = bw[(size_t)o * IN_F + i];
#pragma unroll
    for (int j = 0; j < 11; ++j) v[1 + j] = sw[((size_t)o * IN_F + i) * 11 + j];
    unsigned short sh[NFEAT], sl[NFEAT];
#pragma unroll
    for (int c = 0; c < NFEAT; ++c) {
        __nv_bfloat16 h = __float2bfloat16(v[c]);
        __nv_bfloat16 l = __float2bfloat16(v[c] - __bfloat162float(h));
        sh[c] = __bfloat16_as_ushort(h);  sl[c] = __bfloat16_as_ushort(l);
    }
    size_t off = (size_t)o * KB + (size_t)i * NFEAT;
    unsigned long long* dh = (unsigned long long*)(g_Bh + off);
    unsigned long long* dl = (unsigned long long*)(g_Bl + off);
#pragma unroll
    for (int j = 0; j < 3; ++j) {
        dh[j] = (unsigned long long)sh[4 * j] |
                ((unsigned long long)sh[4 * j + 1] << 16) |
                ((unsigned long long)sh[4 * j + 2] << 32) |
                ((unsigned long long)sh[4 * j + 3] << 48);
        dl[j] = (unsigned long long)sl[4 * j] |
                ((unsigned long long)sl[4 * j + 1] << 16) |
                ((unsigned long long)sl[4 * j + 2] << 32) |
                ((unsigned long long)sl[4 * j + 3] << 48);
    }
}

// ---------------- G: mma.sync bf16 GEMM, 512 threads, 16 warps -------------
// CTA 128x256, warps 4(M) x 4(N), warp tile 32x64, 4 stages, one barrier
// per chunk.  288 uniform chunks: u%3 selects (Ah,Bh),(Ah,Bl),(Al,Bh) at
// k-offset (u/3)*64.  (Identical inner loop to the 543us Round-10 winner.)
__global__ __launch_bounds__(512, 1) void kan_gemm(float* __restrict__ out) {
    extern __shared__ __align__(1024) unsigned char smem[];
    const uint32_t sbase = smem_u32(smem);
    const int tid  = threadIdx.x;
    const int lane = tid & 31;
    const int wid  = tid >> 5;
    const int warpM = wid & 3;          // 0..3 -> 32-row slice
    const int warpN = wid >> 2;         // 0..3 -> 64-col slice
    const int mBase = blockIdx.y * M_TILE;
    const int nBase = blockIdx.x * N_TILE;

    const char* Ah = (const char*)(g_Ah + (size_t)mBase * KB);
    const char* Al = (const char*)(g_Al + (size_t)mBase * KB);
    const char* Bh = (const char*)(g_Bh + (size_t)nBase * KB);
    const char* Bl = (const char*)(g_Bl + (size_t)nBase * KB);

    // ---- cp.async coords: 512 threads, granule (r, c) = (tid>>3, tid&7) ---
    const int gr = tid >> 3, gc = tid & 7;            // gr 0..63
    uint32_t aDst[2], bDst[4];
#pragma unroll
    for (int j = 0; j < 2; ++j) aDst[j] = swz(gr + 64 * j, gc);
#pragma unroll
    for (int j = 0; j < 4; ++j) bDst[j] = (uint32_t)A_BYTES + swz(gr + 64 * j, gc);
    const size_t aRow0 = (size_t)gr * ROWB + gc * 16;
    const size_t aRow1 = (size_t)(gr + 64) * ROWB + gc * 16;
    size_t bRow[4];
#pragma unroll
    for (int j = 0; j < 4; ++j) bRow[j] = (size_t)(gr + 64 * j) * ROWB + gc * 16;

    auto load_stage = [&](int u) {
        const uint32_t st = sbase + (uint32_t)(u & (STG - 1)) * STAGE_BYTES;
        const int sel = u % 3;
        const size_t ch = (size_t)(u / 3) * 128;
        const char* aB = (sel < 2 ? Ah : Al) + ch;
        const char* bB = (sel == 1 ? Bl : Bh) + ch;
        cp16(st + aDst[0], aB + aRow0);
        cp16(st + aDst[1], aB + aRow1);
#pragma unroll
        for (int j = 0; j < 4; ++j) cp16(st + bDst[j], bB + bRow[j]);
    };

    // ---- ldmatrix lane addressing (k-step advance = XOR (s<<5)) -----------
    const int lr = lane & 15;
    const int lc = lane >> 4;
    uint32_t aOff[2], bOff[4];
#pragma unroll
    for (int t = 0; t < 2; ++t)
        aOff[t] = swz(warpM * 32 + t * 16 + lr, lc);
#pragma unroll
    for (int t = 0; t < 4; ++t)
        bOff[t] = (uint32_t)A_BYTES + swz(warpN * 64 + t * 16 + lr, lc);

    float acc[2][8][4];
#pragma unroll
    for (int mt = 0; mt < 2; ++mt)
#pragma unroll
        for (int nt = 0; nt < 8; ++nt)
#pragma unroll
            for (int q = 0; q < 4; ++q) acc[mt][nt][q] = 0.0f;

    for (int i = 0; i < STG - 1; ++i) { load_stage(i); CP_COMMIT(); }

#pragma unroll 1
    for (int i = 0; i < NCH; ++i) {
        CP_WAIT_2();                 // chunk i resident (2 newer groups pending)
        __syncthreads();             // all warps done with the slot being refilled
        const int nc = i + STG - 1;
        if (nc < NCH) load_stage(nc);
        CP_COMMIT();                 // one group per iter (may be empty)

        const uint32_t st = sbase + (uint32_t)(i & (STG - 1)) * STAGE_BYTES;
#pragma unroll
        for (int s = 0; s < 4; ++s) {
            const uint32_t kx = (uint32_t)s << 5;
            uint32_t a[2][4], b[4][4];
#pragma unroll
            for (int t = 0; t < 2; ++t)
                ldsm4(a[t][0], a[t][1], a[t][2], a[t][3], st + (aOff[t] ^ kx));
#pragma unroll
            for (int t = 0; t < 4; ++t)
                ldsm4(b[t][0], b[t][1], b[t][2], b[t][3], st + (bOff[t] ^ kx));
#pragma unroll
            for (int mt = 0; mt < 2; ++mt)
#pragma unroll
                for (int t = 0; t < 4; ++t) {
                    mma16816(acc[mt][2*t][0], acc[mt][2*t][1], acc[mt][2*t][2], acc[mt][2*t][3],
                             a[mt][0], a[mt][1], a[mt][2], a[mt][3], b[t][0], b[t][2]);
                    mma16816(acc[mt][2*t+1][0], acc[mt][2*t+1][1], acc[mt][2*t+1][2], acc[mt][2*t+1][3],
                             a[mt][0], a[mt][1], a[mt][2], a[mt][3], b[t][1], b[t][3]);
                }
        }
    }

    // ---- epilogue: direct STG of register accumulators --------------------
    const int mRow = mBase + warpM * 32 + (lane >> 2);
    const int nCol = nBase + warpN * 64 + (lane & 3) * 2;
#pragma unroll
    for (int mt = 0; mt < 2; ++mt) {
        float* r0 = out + (size_t)(mRow + mt * 16)     * OUT_F + nCol;
        float* r1 = out + (size_t)(mRow + mt * 16 + 8) * OUT_F + nCol;
#pragma unroll
        for (int nt = 0; nt < 8; ++nt) {
            *(float2*)(r0 + nt * 8) = make_float2(acc[mt][nt][0], acc[mt][nt][1]);
            *(float2*)(r1 + nt * 8) = make_float2(acc[mt][nt][2], acc[mt][nt][3]);
        }
    }
}

// ---------------- launch ---------------------------------------------------
extern "C" void kernel_launch(void* const* d_in, const int* in_sizes, int n_in,
                              void* d_out, int out_size) {
    const float* x  = (const float*)d_in[0];
    const float* bw = (const float*)d_in[1];
    const float* sw = (const float*)d_in[2];
    float* out = (float*)d_out;

    cudaFuncSetAttribute(kan_gemm, cudaFuncAttributeMaxDynamicSharedMemorySize,
                         SMEM_TOTAL);

    prep_A<<<(NBAT * IN_F / 2) / 256, 256>>>(x);
    prep_B<<<(OUT_F * IN_F) / 256, 256>>>(bw, sw);
    kan_gemm<<<dim3(OUT_F / N_TILE, NBAT / M_TILE), 512, SMEM_TOTAL>>>(out);
}